// round 15
// baseline (speedup 1.0000x reference)
#include <cuda_runtime.h>
#include <cuda.h>
#include <cuda_bf16.h>
#include <cuda_fp16.h>
#include <cstdint>

// Arch-specific feature gate: tcgen05 only exists on sm_10Xa targets.
// The compute_103 (non-'a') compilation pass must contain NO tcgen05 PTX.
#if defined(__CUDA_ARCH_FEAT_SM103_ALL) || defined(__CUDA_ARCH_FEAT_SM100_ALL) || \
    (defined(__CUDA_ARCH_SPECIFIC__) && (__CUDA_ARCH_SPECIFIC__ >= 1000))
#define USE_TC 1
#else
#define USE_TC 0
#endif

// ============================================================================
// Problem dims / tiling (shared by both paths)
// ============================================================================
#define M_TOTAL 16384
#define N_TOTAL 4096
#define K_TOTAL 4096

#define TILE_M 128
#define TILE_N 128
#define TILE_K 64
#define K_ITERS (K_TOTAL / TILE_K)   // 64
#define STAGES 4
#define STAGE_BYTES 32768            // A 16K + B 16K (fp16)

#define SMEM_TMEM_PTR 0
#define SMEM_FULL(s)  (16 + (s) * 16)
#define SMEM_EMPTY(s) (16 + (s) * 16 + 8)
#define SMEM_DONE     (16 + STAGES * 16)
#define SMEM_A(s)     (1024 + (s) * STAGE_BYTES)
#define SMEM_B(s)     (SMEM_A(s) + 16384)
#define SMEM_TOTAL    (1024 + STAGES * STAGE_BYTES)   // 132096 B

// ============================================================================
// Device scratch (__device__ globals: allocation-free rule)
// ============================================================================
__device__ __align__(1024) __half g_xh[(size_t)M_TOTAL * K_TOTAL];
__device__ __align__(1024) __half g_wh[(size_t)N_TOTAL * K_TOTAL];
__device__ double g_sum_d;
__device__ double g_sumsq_d;
__device__ float  g_thr_lo;
__device__ float  g_thr_hi;

// ============================================================================
// Portable PTX helpers (legal on baseline sm_90+ targets)
// ============================================================================
__device__ __forceinline__ uint32_t smem_u32(const void* p) {
    uint32_t a;
    asm("{ .reg .u64 t; cvta.to.shared.u64 t, %1; cvt.u32.u64 %0, t; }" : "=r"(a) : "l"(p));
    return a;
}

__device__ __forceinline__ uint32_t elect_one() {
    uint32_t p;
    asm volatile(
        "{\n\t.reg .pred p;\n\telect.sync _|p, 0xFFFFFFFF;\n\tselp.b32 %0, 1, 0, p;\n\t}"
        : "=r"(p));
    return p;
}

#define MBARRIER_INIT(addr, count) \
    asm volatile("mbarrier.init.shared.b64 [%0], %1;" :: "r"((uint32_t)(addr)), "r"((uint32_t)(count)) : "memory")

#define MBARRIER_ARRIVE(addr) \
    asm volatile("mbarrier.arrive.shared.b64 _, [%0];" :: "r"((uint32_t)(addr)) : "memory")

#define MBARRIER_EXPECT_TX(addr, bytes) \
    asm volatile("mbarrier.arrive.expect_tx.shared.b64 _, [%0], %1;" :: "r"((uint32_t)(addr)), "r"((uint32_t)(bytes)) : "memory")

#define MBARRIER_WAIT_PARITY(mbar_smem_addr, phase_parity) do { \
    uint32_t _mbar = (uint32_t)(mbar_smem_addr); \
    uint32_t _parity = (uint32_t)(phase_parity); \
    uint32_t _done; \
    asm volatile( \
        "{\n\t.reg .pred p;\n\t" \
        "mbarrier.try_wait.parity.acquire.cta.shared::cta.b64 p, [%1], %2;\n\t" \
        "selp.b32 %0, 1, 0, p;\n\t}" \
        : "=r"(_done) : "r"(_mbar), "r"(_parity) : "memory"); \
    if (!_done) { \
        asm volatile( \
            "{\n\t.reg .pred P1;\n\t" \
            "WAIT_LOOP_%=:\n\t" \
            "mbarrier.try_wait.parity.acquire.cta.shared::cta.b64 P1, [%0], %1, 0x989680;\n\t" \
            "@P1 bra.uni WAIT_DONE_%=;\n\t" \
            "bra.uni WAIT_LOOP_%=;\n\t" \
            "WAIT_DONE_%=:\n\t}" \
            :: "r"(_mbar), "r"(_parity) : "memory"); \
    } \
} while (0)

#define TMA_LOAD_3D(smem_addr, tensor_map, cx, cy, cz, mbar) \
    asm volatile( \
        "cp.async.bulk.tensor.3d.shared::cta.global.tile.mbarrier::complete_tx::bytes " \
        "[%0], [%1, {%2, %3, %4}], [%5];" \
        :: "r"((uint32_t)(smem_addr)), "l"(tensor_map), \
           "r"((int32_t)(cx)), "r"((int32_t)(cy)), "r"((int32_t)(cz)), \
           "r"((uint32_t)(mbar)) \
        : "memory")

#define TMA_PREFETCH(tensor_map) \
    asm volatile("prefetch.tensormap [%0];" :: "l"(tensor_map))

// ============================================================================
// Preprocessing kernels
// ============================================================================
__global__ void zero_stats_kernel() {
    g_sum_d = 0.0;
    g_sumsq_d = 0.0;
}

__global__ void reduce_kernel(const float* __restrict__ w, int n4) {
    double s = 0.0, ss = 0.0;
    const float4* w4 = reinterpret_cast<const float4*>(w);
    for (int i = blockIdx.x * blockDim.x + threadIdx.x; i < n4; i += gridDim.x * blockDim.x) {
        float4 v = w4[i];
        s  += (double)v.x + (double)v.y + (double)v.z + (double)v.w;
        ss += (double)v.x * (double)v.x + (double)v.y * (double)v.y
            + (double)v.z * (double)v.z + (double)v.w * (double)v.w;
    }
    #pragma unroll
    for (int o = 16; o > 0; o >>= 1) {
        s  += __shfl_down_sync(0xFFFFFFFFu, s, o);
        ss += __shfl_down_sync(0xFFFFFFFFu, ss, o);
    }
    __shared__ double sh_s[8], sh_ss[8];
    int wid = threadIdx.x >> 5, lid = threadIdx.x & 31;
    if (lid == 0) { sh_s[wid] = s; sh_ss[wid] = ss; }
    __syncthreads();
    if (wid == 0) {
        s  = (lid < 8) ? sh_s[lid]  : 0.0;
        ss = (lid < 8) ? sh_ss[lid] : 0.0;
        #pragma unroll
        for (int o = 4; o > 0; o >>= 1) {
            s  += __shfl_down_sync(0xFFu, s, o);
            ss += __shfl_down_sync(0xFFu, ss, o);
        }
        if (lid == 0) {
            atomicAdd(&g_sum_d, s);
            atomicAdd(&g_sumsq_d, ss);
        }
    }
}

__global__ void finalize_stats_kernel() {
    const double n = (double)N_TOTAL * (double)K_TOTAL;
    double mean = g_sum_d / n;
    double var = (g_sumsq_d - g_sum_d * g_sum_d / n) / (n - 1.0);  // ddof=1 (torch.std)
    double sd = sqrt(var);
    g_thr_lo = (float)(mean - sd);
    g_thr_hi = (float)(mean + sd);
}

__device__ __forceinline__ float bin_one(float v, float lo, float hi) {
    if (v < lo || v > hi) return v;                           // outlier: keep fp value
    return (v > 0.0f) ? 1.0f : ((v < 0.0f) ? -1.0f : 0.0f);   // sign
}

__global__ void binarize_kernel(const float* __restrict__ w, int n4) {
    const float lo = g_thr_lo, hi = g_thr_hi;
    const float4* w4 = reinterpret_cast<const float4*>(w);
    __half2* out = reinterpret_cast<__half2*>(g_wh);
    for (int i = blockIdx.x * blockDim.x + threadIdx.x; i < n4; i += gridDim.x * blockDim.x) {
        float4 v = w4[i];
        out[2 * i + 0] = __floats2half2_rn(bin_one(v.x, lo, hi), bin_one(v.y, lo, hi));
        out[2 * i + 1] = __floats2half2_rn(bin_one(v.z, lo, hi), bin_one(v.w, lo, hi));
    }
}

__global__ void cvt_x_kernel(const float* __restrict__ x, int n4) {
    const float4* x4 = reinterpret_cast<const float4*>(x);
    __half2* oh = reinterpret_cast<__half2*>(g_xh);
    for (int i = blockIdx.x * blockDim.x + threadIdx.x; i < n4; i += gridDim.x * blockDim.x) {
        float4 v = x4[i];
        oh[2 * i + 0] = __floats2half2_rn(v.x, v.y);
        oh[2 * i + 1] = __floats2half2_rn(v.z, v.w);
    }
}

// ============================================================================
// Unified GEMM kernel: 256 threads, 128x128 tile, 4-stage TMA pipeline.
//   sm_103a cubin -> tcgen05 warp-specialized path (fast).
//   sm_103 cubin  -> ldmatrix + mma.sync.m16n8k16 fp16 path (portable).
// out[m,n] = sum_k xh[m,k] * wh[n,k] + bias[n]
// ============================================================================
__global__ void __launch_bounds__(256, 1) gemm_kernel(
    const __grid_constant__ CUtensorMap tma_a,
    const __grid_constant__ CUtensorMap tma_b,
    const float* __restrict__ bias,
    float* __restrict__ out)
{
    extern __shared__ __align__(1024) char smem[];
    const uint32_t sb = smem_u32(smem);
    const int tid = threadIdx.x;
    const int wid = tid >> 5;
    const int lid = tid & 31;
    const int m_base = blockIdx.y * TILE_M;
    const int n_base = blockIdx.x * TILE_N;

#if USE_TC
    // ------------------------------------------------------------------
    // tcgen05 path: warps 0-3 epilogue, warp 4 TMA producer, warp 5 MMA,
    // warps 6-7 idle.
    // ------------------------------------------------------------------
    if (tid == 0) {
        #pragma unroll
        for (int s = 0; s < STAGES; s++) {
            MBARRIER_INIT(sb + SMEM_FULL(s), 1);
            MBARRIER_INIT(sb + SMEM_EMPTY(s), 1);
        }
        MBARRIER_INIT(sb + SMEM_DONE, 1);
    }
    if (wid == 5) {
        asm volatile("tcgen05.alloc.cta_group::1.sync.aligned.shared::cta.b32 [%0], %1;"
                     :: "r"(sb + SMEM_TMEM_PTR), "r"(256u) : "memory");
        asm volatile("tcgen05.relinquish_alloc_permit.cta_group::1.sync.aligned;");
    }
    __syncthreads();

    uint32_t tmem;
    asm volatile("ld.shared.b32 %0, [%1];" : "=r"(tmem) : "r"(sb + SMEM_TMEM_PTR));

    if (wid == 4) {
        uint32_t e = elect_one();
        if (e) {
            TMA_PREFETCH(&tma_a);
            TMA_PREFETCH(&tma_b);
        }
        int stage = 0, ph = 1;  // fresh barriers: parity-1 wait passes immediately
        for (int it = 0; it < K_ITERS; ++it) {
            if (e) {
                MBARRIER_WAIT_PARITY(sb + SMEM_EMPTY(stage), ph);
                MBARRIER_EXPECT_TX(sb + SMEM_FULL(stage), STAGE_BYTES);
                TMA_LOAD_3D(sb + SMEM_A(stage), &tma_a, it * TILE_K, m_base, 0, sb + SMEM_FULL(stage));
                TMA_LOAD_3D(sb + SMEM_B(stage), &tma_b, it * TILE_K, n_base, 0, sb + SMEM_FULL(stage));
            }
            if (++stage == STAGES) { stage = 0; ph ^= 1; }
        }
    } else if (wid == 5) {
        uint32_t e = elect_one();
        asm volatile("tcgen05.fence::after_thread_sync;" ::: "memory");
        // idesc kind::f16 (fp16 in, fp32 acc): dtype=F32(1<<4), atype=F16(0),
        // btype=F16(0), N/8<<17, M/16<<24
        const uint32_t idesc =
            (1u << 4) | ((TILE_N / 8) << 17) | ((TILE_M / 16) << 24);
        // SW128 K-major SMEM descriptor base bits
        const uint64_t DBASE =
            (uint64_t(2) << 61) | (uint64_t(1) << 46) | (uint64_t(64) << 32) | (uint64_t(1) << 16);
        int stage = 0, ph = 0;
        for (int it = 0; it < K_ITERS; ++it) {
            MBARRIER_WAIT_PARITY(sb + SMEM_FULL(stage), ph);
            if (e) {
                uint64_t da = DBASE | (((sb + SMEM_A(stage)) >> 4) & 0x3FFF);
                uint64_t db = DBASE | (((sb + SMEM_B(stage)) >> 4) & 0x3FFF);
                #pragma unroll
                for (int k = 0; k < 4; ++k) {   // K16 per f16 MMA: desc +2 (32B)
                    uint32_t en = (it == 0 && k == 0) ? 0u : 1u;
                    asm volatile(
                        "{\n\t.reg .pred p;\n\t"
                        "setp.ne.u32 p, %4, 0;\n\t"
                        "tcgen05.mma.cta_group::1.kind::f16 [%0], %1, %2, %3, {%5, %5, %5, %5}, p;\n\t}"
                        :: "r"(tmem), "l"(da + 2 * k), "l"(db + 2 * k), "r"(idesc),
                           "r"(en), "r"(0u)
                        : "memory");
                }
                asm volatile("tcgen05.commit.cta_group::1.mbarrier::arrive::one.shared::cluster.b64 [%0];"
                             :: "r"(sb + SMEM_EMPTY(stage)) : "memory");
            }
            if (++stage == STAGES) { stage = 0; ph ^= 1; }
        }
        if (e)
            asm volatile("tcgen05.commit.cta_group::1.mbarrier::arrive::one.shared::cluster.b64 [%0];"
                         :: "r"(sb + SMEM_DONE) : "memory");
    }

    if (wid < 4) {
        MBARRIER_WAIT_PARITY(sb + SMEM_DONE, 0);
        asm volatile("tcgen05.fence::after_thread_sync;" ::: "memory");
        const int m = m_base + wid * 32 + lid;
        float* orow = out + (size_t)m * N_TOTAL + n_base;
        #pragma unroll
        for (int ch = 0; ch < TILE_N / 32; ++ch) {
            uint32_t r[32];
            asm volatile(
                "tcgen05.ld.sync.aligned.32x32b.x32.b32 "
                "{%0, %1, %2, %3, %4, %5, %6, %7, "
                " %8, %9, %10, %11, %12, %13, %14, %15, "
                " %16, %17, %18, %19, %20, %21, %22, %23, "
                " %24, %25, %26, %27, %28, %29, %30, %31}, [%32];"
                : "=r"(r[0]),  "=r"(r[1]),  "=r"(r[2]),  "=r"(r[3]),
                  "=r"(r[4]),  "=r"(r[5]),  "=r"(r[6]),  "=r"(r[7]),
                  "=r"(r[8]),  "=r"(r[9]),  "=r"(r[10]), "=r"(r[11]),
                  "=r"(r[12]), "=r"(r[13]), "=r"(r[14]), "=r"(r[15]),
                  "=r"(r[16]), "=r"(r[17]), "=r"(r[18]), "=r"(r[19]),
                  "=r"(r[20]), "=r"(r[21]), "=r"(r[22]), "=r"(r[23]),
                  "=r"(r[24]), "=r"(r[25]), "=r"(r[26]), "=r"(r[27]),
                  "=r"(r[28]), "=r"(r[29]), "=r"(r[30]), "=r"(r[31])
                : "r"(tmem + ch * 32));
            asm volatile("tcgen05.wait::ld.sync.aligned;" ::: "memory");
            const float* bp = bias + n_base + ch * 32;
            #pragma unroll
            for (int c = 0; c < 32; c += 4) {
                float4 v;
                v.x = __uint_as_float(r[c + 0]) + __ldg(bp + c + 0);
                v.y = __uint_as_float(r[c + 1]) + __ldg(bp + c + 1);
                v.z = __uint_as_float(r[c + 2]) + __ldg(bp + c + 2);
                v.w = __uint_as_float(r[c + 3]) + __ldg(bp + c + 3);
                __stcs(reinterpret_cast<float4*>(orow + ch * 32 + c), v);
            }
        }
    }

    __syncthreads();
    if (wid == 5) {
        asm volatile("tcgen05.dealloc.cta_group::1.sync.aligned.b32 %0, %1;"
                     :: "r"(tmem), "r"(256u));
    }

#else
    // ------------------------------------------------------------------
    // Portable path: all 8 warps compute with ldmatrix + mma.sync m16n8k16
    // fp16->fp32. Warp grid 2x4: warp tile 64x32.
    // ------------------------------------------------------------------
    if (tid == 0) {
        #pragma unroll
        for (int s = 0; s < STAGES; s++) {
            MBARRIER_INIT(sb + SMEM_FULL(s), 1);
            MBARRIER_INIT(sb + SMEM_EMPTY(s), 256);
        }
    }
    __syncthreads();

    if (tid == 0) {
        TMA_PREFETCH(&tma_a);
        TMA_PREFETCH(&tma_b);
        #pragma unroll
        for (int s = 0; s < STAGES; ++s) {
            MBARRIER_EXPECT_TX(sb + SMEM_FULL(s), STAGE_BYTES);
            TMA_LOAD_3D(sb + SMEM_A(s), &tma_a, s * TILE_K, m_base, 0, sb + SMEM_FULL(s));
            TMA_LOAD_3D(sb + SMEM_B(s), &tma_b, s * TILE_K, n_base, 0, sb + SMEM_FULL(s));
        }
    }

    const int wm = wid >> 2;       // 0..1
    const int wn = wid & 3;        // 0..3
    const int mat = lid >> 3;      // 0..3 (ldmatrix matrix id)
    const int mrow = lid & 7;      // row within 8x8 matrix

    float acc[4][4][4];
    #pragma unroll
    for (int mt = 0; mt < 4; ++mt)
        #pragma unroll
        for (int nt = 0; nt < 4; ++nt)
            #pragma unroll
            for (int c = 0; c < 4; ++c)
                acc[mt][nt][c] = 0.0f;

    int stage = 0, fph = 0, eph = 0;
    for (int it = 0; it < K_ITERS; ++it) {
        MBARRIER_WAIT_PARITY(sb + SMEM_FULL(stage), fph);
        const uint32_t sa = sb + SMEM_A(stage);
        const uint32_t sbb = sb + SMEM_B(stage);

        #pragma unroll
        for (int ks = 0; ks < 4; ++ks) {
            uint32_t af[4][4];
            #pragma unroll
            for (int mt = 0; mt < 4; ++mt) {
                // mats: (m0-7,k0),(m8-15,k0),(m0-7,k+16B),(m8-15,k+16B)
                int m = wm * 64 + mt * 16 + (mat & 1) * 8 + mrow;
                int kb = ks * 32 + (mat >> 1) * 16;
                uint32_t off = (uint32_t)(m * 128 + kb);
                uint32_t addr = sa + (off ^ ((off >> 3) & 0x70));
                asm volatile("ldmatrix.sync.aligned.m8n8.x4.shared.b16 {%0,%1,%2,%3}, [%4];"
                             : "=r"(af[mt][0]), "=r"(af[mt][1]), "=r"(af[mt][2]), "=r"(af[mt][3])
                             : "r"(addr));
            }
            uint32_t bf[2][4];
            #pragma unroll
            for (int np = 0; np < 2; ++np) {
                // mats: (n0-7,k0),(n0-7,k+16B),(n8-15,k0),(n8-15,k+16B)
                int n = wn * 32 + np * 16 + (mat >> 1) * 8 + mrow;
                int kb = ks * 32 + (mat & 1) * 16;
                uint32_t off = (uint32_t)(n * 128 + kb);
                uint32_t addr = sbb + (off ^ ((off >> 3) & 0x70));
                asm volatile("ldmatrix.sync.aligned.m8n8.x4.shared.b16 {%0,%1,%2,%3}, [%4];"
                             : "=r"(bf[np][0]), "=r"(bf[np][1]), "=r"(bf[np][2]), "=r"(bf[np][3])
                             : "r"(addr));
            }
            #pragma unroll
            for (int mt = 0; mt < 4; ++mt) {
                #pragma unroll
                for (int nt = 0; nt < 4; ++nt) {
                    uint32_t b0 = bf[nt >> 1][(nt & 1) * 2 + 0];
                    uint32_t b1 = bf[nt >> 1][(nt & 1) * 2 + 1];
                    asm volatile(
                        "mma.sync.aligned.m16n8k16.row.col.f32.f16.f16.f32 "
                        "{%0,%1,%2,%3}, {%4,%5,%6,%7}, {%8,%9}, {%0,%1,%2,%3};"
                        : "+f"(acc[mt][nt][0]), "+f"(acc[mt][nt][1]),
                          "+f"(acc[mt][nt][2]), "+f"(acc[mt][nt][3])
                        : "r"(af[mt][0]), "r"(af[mt][1]), "r"(af[mt][2]), "r"(af[mt][3]),
                          "r"(b0), "r"(b1));
                }
            }
        }

        MBARRIER_ARRIVE(sb + SMEM_EMPTY(stage));
        if (tid == 0 && it + STAGES < K_ITERS) {
            MBARRIER_WAIT_PARITY(sb + SMEM_EMPTY(stage), eph);
            MBARRIER_EXPECT_TX(sb + SMEM_FULL(stage), STAGE_BYTES);
            TMA_LOAD_3D(sb + SMEM_A(stage), &tma_a, (it + STAGES) * TILE_K, m_base, 0, sb + SMEM_FULL(stage));
            TMA_LOAD_3D(sb + SMEM_B(stage), &tma_b, (it + STAGES) * TILE_K, n_base, 0, sb + SMEM_FULL(stage));
        }
        if (++stage == STAGES) { stage = 0; fph ^= 1; eph ^= 1; }
    }

    // Epilogue: + bias, write fp32 output
    #pragma unroll
    for (int mt = 0; mt < 4; ++mt) {
        #pragma unroll
        for (int nt = 0; nt < 4; ++nt) {
            int m0 = m_base + wm * 64 + mt * 16 + (lid >> 2);
            int n0 = n_base + wn * 32 + nt * 8 + (lid & 3) * 2;
            float b0 = __ldg(bias + n0);
            float b1 = __ldg(bias + n0 + 1);
            float2 v0 = make_float2(acc[mt][nt][0] + b0, acc[mt][nt][1] + b1);
            float2 v1 = make_float2(acc[mt][nt][2] + b0, acc[mt][nt][3] + b1);
            __stcs(reinterpret_cast<float2*>(out + (size_t)m0 * N_TOTAL + n0), v0);
            __stcs(reinterpret_cast<float2*>(out + (size_t)(m0 + 8) * N_TOTAL + n0), v1);
        }
    }
#endif
}

// ============================================================================
// Host: tensormap creation (driver entry point; no -lcuda link needed)
// ============================================================================
typedef CUresult (*tmap_encode_fn)(
    CUtensorMap*, CUtensorMapDataType, cuuint32_t, void*,
    const cuuint64_t*, const cuuint64_t*, const cuuint32_t*, const cuuint32_t*,
    CUtensorMapInterleave, CUtensorMapSwizzle, CUtensorMapL2promotion, CUtensorMapFloatOOBfill);

static void encode_kmajor_map(tmap_encode_fn enc, CUtensorMap* tm, void* base,
                              uint64_t rows, uint32_t box_rows) {
    cuuint64_t dims[3]    = {(cuuint64_t)K_TOTAL, (cuuint64_t)rows, 1};
    cuuint64_t strides[2] = {(cuuint64_t)K_TOTAL * 2, (cuuint64_t)K_TOTAL * rows * 2};
    cuuint32_t box[3]     = {(cuuint32_t)TILE_K, (cuuint32_t)box_rows, 1};
    cuuint32_t es[3]      = {1, 1, 1};
    enc(tm, CU_TENSOR_MAP_DATA_TYPE_FLOAT16, 3, base, dims, strides, box, es,
        CU_TENSOR_MAP_INTERLEAVE_NONE, CU_TENSOR_MAP_SWIZZLE_128B,
        CU_TENSOR_MAP_L2_PROMOTION_L2_128B, CU_TENSOR_MAP_FLOAT_OOB_FILL_NONE);
}

extern "C" void kernel_launch(void* const* d_in, const int* in_sizes, int n_in,
                              void* d_out, int out_size) {
    const float* x    = (const float*)d_in[0];
    const float* w    = (const float*)d_in[1];
    const float* bias = (const float*)d_in[2];
    float* out = (float*)d_out;

    // 1) weight stats (double precision; ddof=1) + binarize -> fp16
    zero_stats_kernel<<<1, 1>>>();
    reduce_kernel<<<1024, 256>>>(w, (N_TOTAL * K_TOTAL) / 4);
    finalize_stats_kernel<<<1, 1>>>();
    binarize_kernel<<<2048, 256>>>(w, (N_TOTAL * K_TOTAL) / 4);

    // 2) x -> fp16
    cvt_x_kernel<<<4096, 256>>>(x, (int)(((size_t)M_TOTAL * K_TOTAL) / 4));

    // 3) tensormaps
    void* p_xh = nullptr; void* p_wh = nullptr;
    cudaGetSymbolAddress(&p_xh, g_xh);
    cudaGetSymbolAddress(&p_wh, g_wh);

    void* fn = nullptr;
    cudaDriverEntryPointQueryResult qr;
    cudaGetDriverEntryPointByVersion("cuTensorMapEncodeTiled", &fn, 12000,
                                     cudaEnableDefault, &qr);
    tmap_encode_fn enc = (tmap_encode_fn)fn;

    CUtensorMap mA, mB;
    encode_kmajor_map(enc, &mA, p_xh, M_TOTAL, TILE_M);
    encode_kmajor_map(enc, &mB, p_wh, N_TOTAL, TILE_N);

    // 4) GEMM — grid.x fast over N-tiles so a wave shares B in L2
    cudaFuncSetAttribute(gemm_kernel, cudaFuncAttributeMaxDynamicSharedMemorySize, SMEM_TOTAL);
    dim3 grid(N_TOTAL / TILE_N, M_TOTAL / TILE_M);
    gemm_kernel<<<grid, 256, SMEM_TOTAL>>>(mA, mB, bias, out);
}